// round 11
// baseline (speedup 1.0000x reference)
#include <cuda_runtime.h>
#include <cstdint>

// FeatureEmbeddingBank: B=4096, 25 reg + 25 cmp tables, L=20, D=64.
// One warp per bag, f-major enumeration (L2-residency of the hot table,
// proven in R7: DRAM bytes 575->466MB). Kernel is LATENCY-bound per R7 ncu
// (no unit >66%). Fix: __launch_bounds__(256,4) gives ptxas 64 regs so all
// 10 LDG.128 gathers front-batch (MLP ~10/warp instead of ~5); row indices
// pre-broadcast; dual accumulators to shorten the FADD chain.
// (Resubmission — R8/R9/R10 runs all died to GPU-acquisition timeouts.)

#define F_REG 25
#define F_TOT 50
#define L_LEN 20
#define EMB_D 64
#define V_REG 50000
#define N_BUCKETS 100000

__global__ __launch_bounds__(256, 4)
void feat_bag_kernel(const int* __restrict__ feats,
                     const float* __restrict__ W_reg,
                     const float* __restrict__ W_cmp,
                     float* __restrict__ out,
                     int n_bags, int B, int b_shift)
{
    const int warp_global = (blockIdx.x * blockDim.x + threadIdx.x) >> 5;
    const int lane = threadIdx.x & 31;
    if (warp_global >= n_bags) return;

    // f-major enumeration; B is a power of two in this problem (4096)
    int f, b;
    if (b_shift >= 0) {
        f = warp_global >> b_shift;
        b = warp_global & (B - 1);
    } else {
        f = warp_global / B;
        b = warp_global - f * B;
    }

    // --- load + map this lane's index (lanes 0..19) ---
    int raw = 0;
    if (lane < L_LEN)
        raw = __ldg(feats + (size_t)b * (F_TOT * L_LEN) + f * L_LEN + lane);

    int idx;
    const float* table;
    if (f < F_REG) {
        idx = min(max(raw, 0), V_REG);
        table = W_reg + (size_t)f * (V_REG + 1) * EMB_D;
    } else {
        int v = max(raw, 0);
        idx = (v > 0) ? ((v - 1) % N_BUCKETS) + 1 : 0;
        table = W_cmp + (size_t)(f - F_REG) * (N_BUCKETS + 1) * EMB_D;
    }

    // nonzero count (mapped idx>0 <=> raw>0 for both table kinds)
    const unsigned pos = __ballot_sync(0xffffffffu, (lane < L_LEN) && (idx > 0));
    const float inv_cnt = 1.0f / (float)max(__popc(pos), 1);

    // --- pre-broadcast the 10 row indices this half-warp gathers ---
    const int half = lane >> 4;          // 0: even rows, 1: odd rows
    const int col  = lane & 15;          // float4 column within the row
    int rows[L_LEN / 2];
#pragma unroll
    for (int i = 0; i < L_LEN / 2; ++i)
        rows[i] = __shfl_sync(0xffffffffu, idx, 2 * i + half);

    // --- gather: 10 independent LDG.128, dual accumulators ---
    const float4* __restrict__ t4 = reinterpret_cast<const float4*>(table);
    float4 acc0 = make_float4(0.f, 0.f, 0.f, 0.f);
    float4 acc1 = make_float4(0.f, 0.f, 0.f, 0.f);
#pragma unroll
    for (int i = 0; i < L_LEN / 2; i += 2) {
        const float4 v0 = __ldg(t4 + (size_t)rows[i]     * (EMB_D / 4) + col);
        const float4 v1 = __ldg(t4 + (size_t)rows[i + 1] * (EMB_D / 4) + col);
        acc0.x += v0.x; acc0.y += v0.y; acc0.z += v0.z; acc0.w += v0.w;
        acc1.x += v1.x; acc1.y += v1.y; acc1.z += v1.z; acc1.w += v1.w;
    }
    acc0.x += acc1.x; acc0.y += acc1.y; acc0.z += acc1.z; acc0.w += acc1.w;

    // combine even-row half with odd-row half (same column, lane ^ 16)
    acc0.x += __shfl_xor_sync(0xffffffffu, acc0.x, 16);
    acc0.y += __shfl_xor_sync(0xffffffffu, acc0.y, 16);
    acc0.z += __shfl_xor_sync(0xffffffffu, acc0.z, 16);
    acc0.w += __shfl_xor_sync(0xffffffffu, acc0.w, 16);

    if (half == 0) {
        acc0.x *= inv_cnt; acc0.y *= inv_cnt; acc0.z *= inv_cnt; acc0.w *= inv_cnt;
        // output stays b-major: [B, 50, D]
        reinterpret_cast<float4*>(out + ((size_t)b * F_TOT + f) * EMB_D)[col] = acc0;
    }
}

extern "C" void kernel_launch(void* const* d_in, const int* in_sizes, int n_in,
                              void* d_out, int out_size)
{
    const int*   feats = (const int*)d_in[0];     // [B, 1000] int32
    const float* W_reg = (const float*)d_in[1];   // [25, 50001, 64] f32
    const float* W_cmp = (const float*)d_in[2];   // [25, 100001, 64] f32
    float*       out   = (float*)d_out;           // [B, 50, 64] f32

    const int B = in_sizes[0] / (F_TOT * L_LEN);
    // power-of-two fast path (B=4096 here)
    int b_shift = -1;
    if ((B & (B - 1)) == 0) {
        b_shift = 0;
        while ((1 << b_shift) < B) ++b_shift;
    }

    const int n_bags = B * F_TOT;                 // 204800
    const int threads = 256;                      // 8 warps = 8 bags / block
    const int blocks = (n_bags * 32 + threads - 1) / threads;

    feat_bag_kernel<<<blocks, threads>>>(feats, W_reg, W_cmp, out,
                                         n_bags, B, b_shift);
}